// round 8
// baseline (speedup 1.0000x reference)
#include <cuda_runtime.h>
#include <cstdint>
#include <cstddef>

#define NN 8192
#define KC 16
#define DD 64

#define NIC 37                      // i-chunks (~222 rows each)
#define PADI 224                    // max rows, rounded to 4
#define NJB 8                       // j-blocks of 1024
#define GRID2 (NIC * NJB)           // 296 blocks = 2/SM * 148
#define TPB 512                     // 16 warps per block

static __device__ __align__(16) float g_piT[KC][NN];              // u: [k][j]
static __device__ __align__(16) unsigned long long g_vd[NN * KC]; // pack2(v,v)
static __device__ float g_partials[GRID2];

// ------------------------------------------------------------------
// helpers
// ------------------------------------------------------------------
__device__ __forceinline__ unsigned long long pack2(float x, float y) {
    unsigned long long r;
    asm("mov.b64 %0, {%1, %2};" : "=l"(r) : "f"(x), "f"(y));
    return r;
}
__device__ __forceinline__ void unpack2(unsigned long long p, float& x, float& y) {
    asm("mov.b64 {%0, %1}, %2;" : "=f"(x), "=f"(y) : "l"(p));
}
__device__ __forceinline__ void fma2(unsigned long long& d, unsigned long long a,
                                     unsigned long long b) {
    asm("fma.rn.f32x2 %0, %1, %2, %0;" : "+l"(d) : "l"(a), "l"(b));
}

// ------------------------------------------------------------------
// Kernel 1: distances -> softmax pi -> write piT (u) and v-dup
// 256 threads = 16 k-lanes x 16 node-slots, 2 nodes per thread (ILP)
// sum_k softmax = 1 exactly, so v = c1*pi - c2
// ------------------------------------------------------------------
__global__ void __launch_bounds__(256)
pi_kernel(const float* __restrict__ emb,    // (3, NN, DD)
          const float* __restrict__ comm,   // (KC, DD)
          const float* __restrict__ alpha_p) {
    __shared__ float4 c4s[DD / 4][KC];      // [q][k]
    const int tid  = threadIdx.x;
    const int k    = tid & 15;
    const int nloc = tid >> 4;
    const int n0   = blockIdx.x * 32 + nloc;
    const int n1   = n0 + 16;

    {
        const int kk = tid >> 4;
        const int q  = tid & 15;
        c4s[q][kk] = reinterpret_cast<const float4*>(comm)[kk * 16 + q];
    }
    __syncthreads();

    const float LOR_MIN = (float)(1.0 + 1e-7);
    const float CLIP_LO = (float)(-1.0 + 1e-7);
    const float CLIP_HI = (float)(1.0 - 1e-7);

    const float4* A0 = reinterpret_cast<const float4*>(emb) + (size_t)n0 * 16;
    const float4* B0 = A0 + (size_t)NN * 16;
    const float4* C0 = B0 + (size_t)NN * 16;
    const float4* A1 = reinterpret_cast<const float4*>(emb) + (size_t)n1 * 16;
    const float4* B1 = A1 + (size_t)NN * 16;
    const float4* C1 = B1 + (size_t)NN * 16;

    float dE0 = 0.f, xn0 = 0.f, dL0 = 0.f, dS0 = 0.f;
    float dE1 = 0.f, xn1 = 0.f, dL1 = 0.f, dS1 = 0.f;
    float cn = 0.f;

    #pragma unroll
    for (int q = 0; q < 16; ++q) {
        float4 c = c4s[q][k];
        cn = fmaf(c.x, c.x, cn);
        cn = fmaf(c.y, c.y, cn);
        cn = fmaf(c.z, c.z, cn);
        cn = fmaf(c.w, c.w, cn);

        float4 a = A0[q];
        dE0 = fmaf(a.x, c.x, dE0); dE0 = fmaf(a.y, c.y, dE0);
        dE0 = fmaf(a.z, c.z, dE0); dE0 = fmaf(a.w, c.w, dE0);
        xn0 = fmaf(a.x, a.x, xn0); xn0 = fmaf(a.y, a.y, xn0);
        xn0 = fmaf(a.z, a.z, xn0); xn0 = fmaf(a.w, a.w, xn0);
        float4 b = B0[q];
        dL0 = fmaf(b.x, c.x, dL0); dL0 = fmaf(b.y, c.y, dL0);
        dL0 = fmaf(b.z, c.z, dL0); dL0 = fmaf(b.w, c.w, dL0);
        float4 d = C0[q];
        dS0 = fmaf(d.x, c.x, dS0); dS0 = fmaf(d.y, c.y, dS0);
        dS0 = fmaf(d.z, c.z, dS0); dS0 = fmaf(d.w, c.w, dS0);

        float4 a1 = A1[q];
        dE1 = fmaf(a1.x, c.x, dE1); dE1 = fmaf(a1.y, c.y, dE1);
        dE1 = fmaf(a1.z, c.z, dE1); dE1 = fmaf(a1.w, c.w, dE1);
        xn1 = fmaf(a1.x, a1.x, xn1); xn1 = fmaf(a1.y, a1.y, xn1);
        xn1 = fmaf(a1.z, a1.z, xn1); xn1 = fmaf(a1.w, a1.w, xn1);
        float4 b1 = B1[q];
        dL1 = fmaf(b1.x, c.x, dL1); dL1 = fmaf(b1.y, c.y, dL1);
        dL1 = fmaf(b1.z, c.z, dL1); dL1 = fmaf(b1.w, c.w, dL1);
        float4 d1 = C1[q];
        dS1 = fmaf(d1.x, c.x, dS1); dS1 = fmaf(d1.y, c.y, dS1);
        dS1 = fmaf(d1.z, c.z, dS1); dS1 = fmaf(d1.w, c.w, dS1);
    }

    const float c00 = c4s[0][k].x;

    float d2_0 = fmaxf(xn0 - 2.f * dE0 + cn, 0.f);
    float d2_1 = fmaxf(xn1 - 2.f * dE1 + cn, 0.f);

    float lip0 = dL0 - 2.f * B0[0].x * c00;
    float lip1 = dL1 - 2.f * B1[0].x * c00;
    float dl0 = acoshf(fmaxf(-lip0, LOR_MIN));
    float dl1 = acoshf(fmaxf(-lip1, LOR_MIN));
    d2_0 = fmaf(dl0, dl0, d2_0);
    d2_1 = fmaf(dl1, dl1, d2_1);

    float ds0 = acosf(fminf(fmaxf(dS0, CLIP_LO), CLIP_HI));
    float ds1 = acosf(fminf(fmaxf(dS1, CLIP_LO), CLIP_HI));
    d2_0 = fmaf(ds0, ds0, d2_0);
    d2_1 = fmaf(ds1, ds1, d2_1);

    const float dn0 = sqrtf(d2_0);
    const float dn1 = sqrtf(d2_1);

    float m0 = dn0, m1 = dn1;
    #pragma unroll
    for (int off = 8; off >= 1; off >>= 1) {
        m0 = fmaxf(m0, __shfl_xor_sync(0xffffffffu, m0, off, 16));
        m1 = fmaxf(m1, __shfl_xor_sync(0xffffffffu, m1, off, 16));
    }
    float e0 = expf(dn0 - m0);
    float e1 = expf(dn1 - m1);
    float es0 = e0, es1 = e1;
    #pragma unroll
    for (int off = 8; off >= 1; off >>= 1) {
        es0 += __shfl_xor_sync(0xffffffffu, es0, off, 16);
        es1 += __shfl_xor_sync(0xffffffffu, es1, off, 16);
    }
    const float pi0 = e0 / es0;
    const float pi1 = e1 / es1;

    const float a  = alpha_p[0];
    const float c1 = a * (1.f / ((float)KC * (float)NN));
    const float c2 = 1.f / ((float)KC * (float)KC * (float)NN);
    const float v0 = fmaf(c1, pi0, -c2);
    const float v1 = fmaf(c1, pi1, -c2);

    g_piT[k][n0] = pi0;
    g_piT[k][n1] = pi1;
    g_vd[(size_t)n0 * KC + k] = pack2(v0, v0);
    g_vd[(size_t)n1 * KC + k] = pack2(v1, v1);
}

// ------------------------------------------------------------------
// Kernel 2: warp owns 64 j's (u in 32 regs); block = 16 warps, 1024 j's.
// R streamed once (LDG.64/warp/row = 256B coalesced); MLP=4 prefetch.
// 2 blocks/SM x 512 thr -> 8 warps/SMSP; reg budget <= 64 (no spill).
// ------------------------------------------------------------------
__global__ void __launch_bounds__(TPB, 2)
bilinear_kernel(const float* __restrict__ R) {
    __shared__ __align__(16) unsigned long long svd[PADI * KC];  // 28KB
    __shared__ float red[TPB];

    const int tid  = threadIdx.x;
    const int warp = tid >> 5;
    const int lane = tid & 31;
    const int b    = blockIdx.x;
    const int ic   = b >> 3;                       // 0..36
    const int jb   = b & 7;                        // 0..7
    const int jbase = jb * 1024 + warp * 64 + lane * 2;

    const int i0 = (ic * NN) / NIC;
    const int i1 = ((ic + 1) * NN) / NIC;
    const int nrows = i1 - i0;
    const int nr4 = (nrows + 3) & ~3;

    // stage v-dup chunk into smem; zero-pad rows [nrows, PADI)
    {
        const ulonglong2* src =
            reinterpret_cast<const ulonglong2*>(g_vd + (size_t)i0 * KC);
        ulonglong2* dst = reinterpret_cast<ulonglong2*>(svd);
        const int cnt = nrows * (KC / 2);
        for (int idx = tid; idx < cnt; idx += TPB) dst[idx] = src[idx];
        for (int idx = cnt + tid; idx < PADI * (KC / 2); idx += TPB)
            dst[idx] = make_ulonglong2(0ull, 0ull);
    }

    // u: this warp's 2 j's per lane, all 16 k -> 32 regs
    unsigned long long u[KC];
    #pragma unroll
    for (int k = 0; k < KC; ++k)
        u[k] = *reinterpret_cast<const unsigned long long*>(&g_piT[k][jbase]);

    __syncthreads();

    const char* Rbase = reinterpret_cast<const char*>(R + (size_t)i0 * NN + jbase);
    const size_t rstride = (size_t)NN * sizeof(float);
    const int rmax = nrows - 1;

    unsigned long long acc0 = 0, acc1 = 0;

    #define RADDR(rr) reinterpret_cast<const unsigned long long*>( \
        Rbase + (size_t)min((rr), rmax) * rstride)

    unsigned long long Rb0 = *RADDR(0);
    unsigned long long Rb1 = *RADDR(1);
    unsigned long long Rb2 = *RADDR(2);
    unsigned long long Rb3 = *RADDR(3);

    #define ROWSTEP(RV, rr) do {                                          \
        const ulonglong2* vp =                                            \
            reinterpret_cast<const ulonglong2*>(svd + (size_t)(rr) * KC); \
        unsigned long long sa = 0, sb = 0;                                \
        _Pragma("unroll")                                                 \
        for (int p = 0; p < 8; ++p) {                                     \
            ulonglong2 vv = vp[p];                                        \
            fma2(sa, u[2 * p + 0], vv.x);                                 \
            fma2(sb, u[2 * p + 1], vv.y);                                 \
        }                                                                 \
        fma2(acc0, (RV), sa);                                             \
        fma2(acc1, (RV), sb);                                             \
    } while (0)

    for (int rb = 0; rb < nr4; rb += 4) {
        unsigned long long R0 = Rb0; Rb0 = *RADDR(rb + 4);
        unsigned long long R1 = Rb1; Rb1 = *RADDR(rb + 5);
        unsigned long long R2 = Rb2; Rb2 = *RADDR(rb + 6);
        unsigned long long R3 = Rb3; Rb3 = *RADDR(rb + 7);
        ROWSTEP(R0, rb + 0);
        ROWSTEP(R1, rb + 1);
        ROWSTEP(R2, rb + 2);
        ROWSTEP(R3, rb + 3);
    }

    #undef ROWSTEP
    #undef RADDR

    // combine pairs (fixed order -> deterministic)
    float lo, hi;
    unpack2(acc0, lo, hi);
    float total = lo + hi;
    unpack2(acc1, lo, hi);
    total += lo + hi;

    red[tid] = total;
    __syncthreads();
    #pragma unroll
    for (int off = TPB / 2; off >= 1; off >>= 1) {
        if (tid < off) red[tid] += red[tid + off];
        __syncthreads();
    }
    if (tid == 0) g_partials[b] = red[0];
}

// ------------------------------------------------------------------
// Kernel 3: finalize — sum GRID2 partials, write scalar
// ------------------------------------------------------------------
__global__ void __launch_bounds__(256)
finalize_kernel(float* __restrict__ out) {
    __shared__ float red[256];
    const int tid = threadIdx.x;
    float a = 0.f;
    for (int i = tid; i < GRID2; i += 256) a += g_partials[i];
    red[tid] = a;
    __syncthreads();
    #pragma unroll
    for (int off = 128; off >= 1; off >>= 1) {
        if (tid < off) red[tid] += red[tid + off];
        __syncthreads();
    }
    if (tid == 0) out[0] = red[0];
}

// ------------------------------------------------------------------
extern "C" void kernel_launch(void* const* d_in, const int* in_sizes, int n_in,
                              void* d_out, int out_size) {
    const float* emb   = (const float*)d_in[0];   // (3, 8192, 64)
    const float* comm  = (const float*)d_in[1];   // (16, 64)
    const float* ricci = (const float*)d_in[2];   // (8192, 8192)
    const float* alpha = (const float*)d_in[3];   // scalar
    float* out = (float*)d_out;

    pi_kernel<<<NN / 32, 256>>>(emb, comm, alpha);
    bilinear_kernel<<<GRID2, TPB>>>(ricci);
    finalize_kernel<<<1, 256>>>(out);
}